// round 5
// baseline (speedup 1.0000x reference)
#include <cuda_runtime.h>
#include <math.h>

#define BROWS 16
#define NSAMP 524288
#define NP    (NSAMP + 16)      // padded row stride (padding stays zero-init)
#define LSEG  128
#define SSEG  4096              // segments per row
#define NMAPS (SSEG - 1)        // maps actually consumed per row
#define TSTR  160               // floats per map: [0]=t0, [32..159]=t1..t128 (640B)
#define PF    8                 // k_bound prefetch depth (compile-time slots)

__device__ float g_v[BROWS * NP];                    // q * x_L, row-major padded
__device__ float g_t[(size_t)BROWS * SSEG * TSTR];   // per-segment map intercepts
__device__ float g_U[BROWS * SSEG];                  // exact segment seed states

__device__ __forceinline__ float sanitize(float v) {
    if (isnan(v)) v = 0.0f;
    if (v == 0.0f) v = 1e-10f;
    return v;
}

struct RowP { float aA, aR, q, thr, ratio, invr, knee, gmk; };

__device__ __forceinline__ RowP row_params(const float* __restrict__ p, int b) {
    float p0 = sanitize(p[b * 6 + 0]);
    float p1 = sanitize(p[b * 6 + 1]);
    float p2 = sanitize(p[b * 6 + 2]);
    float p3 = sanitize(p[b * 6 + 3]);
    float p4 = sanitize(p[b * 6 + 4]);
    float p5 = sanitize(p[b * 6 + 5]);
    RowP r;
    r.thr = -p0 * 60.0f;
    r.ratio = p1 * 10.0f;
    r.invr = 1.0f / r.ratio;
    float attack  = fmaxf(p2 / 10.0f, 1e-4f);
    float release = fmaxf(p3 * 3.0f, 0.005f);
    const float L9 = 2.1972245773362196f;
    r.aA = expf(-L9 / (44100.0f * attack));
    r.aR = expf(-L9 / (44100.0f * release));
    r.q = (r.aA <= r.aR) ? 1.0f : -1.0f;
    r.knee = p4 * 24.0f;
    float mk = p5 * 20.0f;
    r.gmk = exp10f(mk / 20.0f);
    return r;
}

__device__ __forceinline__ float xl_of(float xi, const RowP& r) {
    float ax = fabsf(xi) + 1e-8f;
    float xg = 20.0f * log10f(ax);
    xg = fmaxf(xg, -96.0f);
    float d = xg - r.thr;
    float td = 2.0f * d;
    float xl;
    if (td < -r.knee) {
        xl = 0.0f;
    } else if (td > r.knee) {
        xl = d - d / r.ratio;
    } else {
        float h = (d + r.knee) * 0.5f;
        xl = -(r.invr * h * h) / (2.0f * r.knee);
    }
    return xl;
}

// ---------------- Kernel 1: v = q * x_L, row-major padded ------------------
__global__ void k_xl(const float* __restrict__ x, const float* __restrict__ p) {
    int tid = blockIdx.x * blockDim.x + threadIdx.x;
    const int NG = NSAMP / 4;
    if (tid >= BROWS * NG) return;
    int b = tid / NG;
    int n4 = tid % NG;
    RowP r = row_params(p, b);
    float4 xv = reinterpret_cast<const float4*>(x)[(size_t)b * NG + n4];
    float4 v;
    v.x = r.q * xl_of(xv.x, r);
    v.y = r.q * xl_of(xv.y, r);
    v.z = r.q * xl_of(xv.z, r);
    v.w = r.q * xl_of(xv.w, r);
    reinterpret_cast<float4*>(g_v)[(size_t)b * (NP / 4) + n4] = v;
}

// ---------------- Kernel 2: max-affine maps, TWO per warp ------------------
// Map of segment s: u_{128(s+1)} = max_{j=0..128}( sig_j * u_{128 s} + t_j ),
// wavefront: t'_j = c + max(aA t_j, aR t_{j-1});  t'_0 = c + aA t_0.
// Two independent wavefronts interleaved per warp for ILP.
__global__ void __launch_bounds__(256) k_map(const float* __restrict__ p) {
    __shared__ float csm[8][2][LSEG];
    int wid  = threadIdx.x >> 5;
    int lane = threadIdx.x & 31;
    int w = blockIdx.x * 8 + wid;          // 0 .. 32767
    int b  = w >> 11;                       // 2048 warps per row
    int s0 = (w & 2047) * 2;                // maps s0, s0+1 (s=4095 computed, unused)
    RowP rp = row_params(p, b);
    float aA = rp.aA, aR = rp.aR;

    const float* v0 = g_v + (size_t)b * NP + s0 * LSEG;
    const float* v1 = v0 + LSEG;
    for (int i = lane; i < LSEG; i += 32) {
        csm[wid][0][i] = v0[i + 1] - v0[i + 2];
        csm[wid][1][i] = v1[i + 1] - v1[i + 2];
    }
    __syncwarp();

    const float NI = __int_as_float(0xff800000);   // -inf sentinel
    float ta0 = 0.0f, tb0 = 0.0f;                   // line j=0 of each map
    float a0 = NI, a1 = NI, a2 = NI, a3 = NI;       // map A: lines 4*lane+1..+4
    float b0 = NI, b1 = NI, b2 = NI, b3 = NI;       // map B: lines 4*lane+1..+4

#pragma unroll 4
    for (int i = 0; i < LSEG; ++i) {
        float ca = csm[wid][0][i];
        float cb = csm[wid][1][i];
        float na = __shfl_up_sync(0xffffffffu, a3, 1);
        float nb = __shfl_up_sync(0xffffffffu, b3, 1);
        if (lane == 0) { na = ta0; nb = tb0; }
        a3 = fmaxf(fmaf(aA, a3, ca), fmaf(aR, a2, ca));
        b3 = fmaxf(fmaf(aA, b3, cb), fmaf(aR, b2, cb));
        a2 = fmaxf(fmaf(aA, a2, ca), fmaf(aR, a1, ca));
        b2 = fmaxf(fmaf(aA, b2, cb), fmaf(aR, b1, cb));
        a1 = fmaxf(fmaf(aA, a1, ca), fmaf(aR, a0, ca));
        b1 = fmaxf(fmaf(aA, b1, cb), fmaf(aR, b0, cb));
        a0 = fmaxf(fmaf(aA, a0, ca), fmaf(aR, na, ca));
        b0 = fmaxf(fmaf(aA, b0, cb), fmaf(aR, nb, cb));
        ta0 = fmaf(aA, ta0, ca);
        tb0 = fmaf(aA, tb0, cb);
    }

    float* TA = g_t + ((size_t)b * SSEG + s0) * TSTR;
    float* TB = TA + TSTR;
    if (lane == 0) { TA[0] = ta0; TB[0] = tb0; }
    reinterpret_cast<float4*>(TA + 32)[lane] = make_float4(a0, a1, a2, a3);
    reinterpret_cast<float4*>(TB + 32)[lane] = make_float4(b0, b1, b2, b3);
}

// ---------------- Kernel 3: chain segment boundaries (warp/row) ------------
__global__ void k_bound(const float* __restrict__ p) {
    int b = blockIdx.x;
    int lane = threadIdx.x;
    RowP rp = row_params(p, b);
    float la = log2f(rp.aA), lr = log2f(rp.aR);
    float sig[4];
#pragma unroll
    for (int i = 0; i < 4; i++) {
        float j = (float)(4 * lane + 1 + i);
        sig[i] = exp2f(la * ((float)LSEG - j) + lr * j);
    }
    float sig0 = (lane == 0) ? exp2f(la * (float)LSEG) : 0.0f;
    const float NI = __int_as_float(0xff800000);

    float u = -g_v[(size_t)b * NP + 1];          // u_0 = -v[1]
    if (lane == 0) g_U[b * SSEG + 0] = u;

    const float* Tb = g_t + (size_t)b * SSEG * TSTR;
    float4 ta[PF];
    float t0a[PF];
#pragma unroll
    for (int k = 0; k < PF; k++) {
        const float* ts = Tb + (size_t)k * TSTR;
        ta[k]  = reinterpret_cast<const float4*>(ts + 32)[lane];
        t0a[k] = ts[0];
    }

    // SSEG iterations total; last one (s = NMAPS) computes a discarded value.
    for (int sb = 0; sb < SSEG; sb += PF) {
#pragma unroll
        for (int j = 0; j < PF; ++j) {           // compile-time slot -> regs
            int s = sb + j;
            float4 A = ta[j];
            float t0v = (lane == 0) ? t0a[j] : NI;
            int sp = s + PF;
            if (sp < SSEG) {
                const float* ts = Tb + (size_t)sp * TSTR;
                ta[j]  = reinterpret_cast<const float4*>(ts + 32)[lane];
                t0a[j] = ts[0];
            }
            float m0 = fmaf(sig[0], u, A.x);
            float m1 = fmaf(sig[1], u, A.y);
            float m2 = fmaf(sig[2], u, A.z);
            float m3 = fmaf(sig[3], u, A.w);
            float m4 = fmaf(sig0, u, t0v);       // lanes!=0: fma(0,u,-inf) = -inf
            float m = fmaxf(fmaxf(fmaxf(m0, m1), fmaxf(m2, m3)), m4);
            // monotone float->u32 map, warp allreduce max (REDUX.UMAX), map back
            unsigned bm = __float_as_uint(m);
            unsigned mm = bm ^ (((unsigned)((int)bm >> 31)) | 0x80000000u);
            unsigned rm = __reduce_max_sync(0xffffffffu, mm);
            u = __uint_as_float((rm & 0x80000000u) ? (rm ^ 0x80000000u) : ~rm);
            if (lane == 0 && (s + 1) < SSEG) g_U[b * SSEG + s + 1] = u;
        }
    }
}

// ---------------- Kernel 4: per-segment rerun + fused output ---------------
#define STEPF(C) do { float c_ = (C); u = fmaxf(fmaf(aA, u, c_), fmaf(aR, u, c_)); } while (0)

__device__ __forceinline__ float emitv(float xi, float w, float q, float gmk) {
    float y = fmaxf(q * w, -96.0f);
    float val = xi * exp10f(-y / 20.0f) * gmk;
    return isfinite(val) ? val : 0.0f;
}

__global__ void k_apply(const float* __restrict__ x, const float* __restrict__ p,
                        float* __restrict__ out) {
    int tid = blockIdx.x * blockDim.x + threadIdx.x;   // 65536 threads
    int b = tid >> 12;
    int s = tid & (SSEG - 1);
    RowP r = row_params(p, b);
    float aA = r.aA, aR = r.aR, q = r.q, gmk = r.gmk;
    float u = g_U[(b << 12) + s];

    const float4* V4 = reinterpret_cast<const float4*>(g_v) + (size_t)b * (NP / 4) + s * (LSEG / 4);
    const float4* X4 = reinterpret_cast<const float4*>(x) + (size_t)b * (NSAMP / 4) + s * (LSEG / 4);
    float4* O4 = reinterpret_cast<float4*>(out) + (size_t)b * (NSAMP / 4) + s * (LSEG / 4);

    float4 cur = V4[0];
#pragma unroll 4
    for (int g = 0; g < LSEG / 4; ++g) {
        float4 nxt = V4[g + 1];          // last read hits zero padding (v_N = 0)
        float4 xv = X4[g];
        float4 o;
        o.x = emitv(xv.x, u + cur.y, q, gmk); STEPF(cur.y - cur.z);
        o.y = emitv(xv.y, u + cur.z, q, gmk); STEPF(cur.z - cur.w);
        o.z = emitv(xv.z, u + cur.w, q, gmk); STEPF(cur.w - nxt.x);
        o.w = emitv(xv.w, u + nxt.x, q, gmk); STEPF(nxt.x - nxt.y);
        O4[g] = o;
        cur = nxt;
    }
}

extern "C" void kernel_launch(void* const* d_in, const int* in_sizes, int n_in,
                              void* d_out, int out_size) {
    const float* x = (const float*)d_in[0];      // [16, 524288] f32
    const float* p = (const float*)d_in[1];      // [16, 6] f32
    float* out = (float*)d_out;

    int total = BROWS * (NSAMP / 4);
    k_xl<<<(total + 255) / 256, 256>>>(x, p);
    k_map<<<4096, 256>>>(p);                     // 8 warps/block, 2 maps/warp
    k_bound<<<BROWS, 32>>>(p);
    k_apply<<<(BROWS * SSEG) / 256, 256>>>(x, p, out);
}

// round 6
// speedup vs baseline: 1.4771x; 1.4771x over previous
#include <cuda_runtime.h>
#include <math.h>

#define BROWS 16
#define NSAMP 524288
#define NP    (NSAMP + 16)      // padded row stride (padding stays zero-init)
#define LSEG  128
#define SSEG  4096              // segments per row
#define NMAPS (SSEG - 1)        // maps actually consumed per row
#define TSTR  160               // floats per map: [0]=t0, [32..159]=t1..t128 (640B)
#define PF    8                 // k_bound prefetch depth (compile-time slots)

__device__ float g_v[BROWS * NP];                    // q * x_L, row-major padded
__device__ float g_t[(size_t)BROWS * SSEG * TSTR];   // per-segment map intercepts
__device__ float g_U[BROWS * SSEG];                  // exact segment seed states

__device__ __forceinline__ float sanitize(float v) {
    if (isnan(v)) v = 0.0f;
    if (v == 0.0f) v = 1e-10f;
    return v;
}

struct RowP { float aA, aR, q, thr, ratio, invr, knee, gmk; };

__device__ __forceinline__ RowP row_params(const float* __restrict__ p, int b) {
    float p0 = sanitize(p[b * 6 + 0]);
    float p1 = sanitize(p[b * 6 + 1]);
    float p2 = sanitize(p[b * 6 + 2]);
    float p3 = sanitize(p[b * 6 + 3]);
    float p4 = sanitize(p[b * 6 + 4]);
    float p5 = sanitize(p[b * 6 + 5]);
    RowP r;
    r.thr = -p0 * 60.0f;
    r.ratio = p1 * 10.0f;
    r.invr = 1.0f / r.ratio;
    float attack  = fmaxf(p2 / 10.0f, 1e-4f);
    float release = fmaxf(p3 * 3.0f, 0.005f);
    const float L9 = 2.1972245773362196f;
    r.aA = expf(-L9 / (44100.0f * attack));
    r.aR = expf(-L9 / (44100.0f * release));
    r.q = (r.aA <= r.aR) ? 1.0f : -1.0f;
    r.knee = p4 * 24.0f;
    float mk = p5 * 20.0f;
    r.gmk = exp10f(mk / 20.0f);
    return r;
}

__device__ __forceinline__ float xl_of(float xi, const RowP& r) {
    float ax = fabsf(xi) + 1e-8f;
    float xg = 20.0f * log10f(ax);
    xg = fmaxf(xg, -96.0f);
    float d = xg - r.thr;
    float td = 2.0f * d;
    float xl;
    if (td < -r.knee) {
        xl = 0.0f;
    } else if (td > r.knee) {
        xl = d - d / r.ratio;
    } else {
        float h = (d + r.knee) * 0.5f;
        xl = -(r.invr * h * h) / (2.0f * r.knee);
    }
    return xl;
}

// ---------------- Kernel 1: v = q * x_L, row-major padded ------------------
__global__ void k_xl(const float* __restrict__ x, const float* __restrict__ p) {
    int tid = blockIdx.x * blockDim.x + threadIdx.x;
    const int NG = NSAMP / 4;
    if (tid >= BROWS * NG) return;
    int b = tid / NG;
    int n4 = tid % NG;
    RowP r = row_params(p, b);
    float4 xv = reinterpret_cast<const float4*>(x)[(size_t)b * NG + n4];
    float4 v;
    v.x = r.q * xl_of(xv.x, r);
    v.y = r.q * xl_of(xv.y, r);
    v.z = r.q * xl_of(xv.z, r);
    v.w = r.q * xl_of(xv.w, r);
    reinterpret_cast<float4*>(g_v)[(size_t)b * (NP / 4) + n4] = v;
}

// ---------------- Kernel 2: max-affine maps, TWO per warp ------------------
// Map of segment s: u_{128(s+1)} = max_{j=0..128}( sig_j * u_{128 s} + t_j ),
// wavefront: t'_j = c + max(aA t_j, aR t_{j-1});  t'_0 = c + aA t_0.
// Two independent wavefronts interleaved per warp for ILP.
__global__ void __launch_bounds__(256) k_map(const float* __restrict__ p) {
    __shared__ float csm[8][2][LSEG];
    int wid  = threadIdx.x >> 5;
    int lane = threadIdx.x & 31;
    int w = blockIdx.x * 8 + wid;          // 0 .. 32767
    int b  = w >> 11;                       // 2048 warps per row
    int s0 = (w & 2047) * 2;                // maps s0, s0+1 (s=4095 computed, unused)
    RowP rp = row_params(p, b);
    float aA = rp.aA, aR = rp.aR;

    const float* v0 = g_v + (size_t)b * NP + s0 * LSEG;
    const float* v1 = v0 + LSEG;
    for (int i = lane; i < LSEG; i += 32) {
        csm[wid][0][i] = v0[i + 1] - v0[i + 2];
        csm[wid][1][i] = v1[i + 1] - v1[i + 2];
    }
    __syncwarp();

    const float NI = __int_as_float(0xff800000);   // -inf sentinel
    float ta0 = 0.0f, tb0 = 0.0f;                   // line j=0 of each map
    float a0 = NI, a1 = NI, a2 = NI, a3 = NI;       // map A: lines 4*lane+1..+4
    float b0 = NI, b1 = NI, b2 = NI, b3 = NI;       // map B: lines 4*lane+1..+4

#pragma unroll 4
    for (int i = 0; i < LSEG; ++i) {
        float ca = csm[wid][0][i];
        float cb = csm[wid][1][i];
        float na = __shfl_up_sync(0xffffffffu, a3, 1);
        float nb = __shfl_up_sync(0xffffffffu, b3, 1);
        if (lane == 0) { na = ta0; nb = tb0; }
        a3 = fmaxf(fmaf(aA, a3, ca), fmaf(aR, a2, ca));
        b3 = fmaxf(fmaf(aA, b3, cb), fmaf(aR, b2, cb));
        a2 = fmaxf(fmaf(aA, a2, ca), fmaf(aR, a1, ca));
        b2 = fmaxf(fmaf(aA, b2, cb), fmaf(aR, b1, cb));
        a1 = fmaxf(fmaf(aA, a1, ca), fmaf(aR, a0, ca));
        b1 = fmaxf(fmaf(aA, b1, cb), fmaf(aR, b0, cb));
        a0 = fmaxf(fmaf(aA, a0, ca), fmaf(aR, na, ca));
        b0 = fmaxf(fmaf(aA, b0, cb), fmaf(aR, nb, cb));
        ta0 = fmaf(aA, ta0, ca);
        tb0 = fmaf(aA, tb0, cb);
    }

    float* TA = g_t + ((size_t)b * SSEG + s0) * TSTR;
    float* TB = TA + TSTR;
    if (lane == 0) { TA[0] = ta0; TB[0] = tb0; }
    reinterpret_cast<float4*>(TA + 32)[lane] = make_float4(a0, a1, a2, a3);
    reinterpret_cast<float4*>(TB + 32)[lane] = make_float4(b0, b1, b2, b3);
}

// ---------------- Kernel 3: chain segment boundaries (warp/row) ------------
__global__ void k_bound(const float* __restrict__ p) {
    int b = blockIdx.x;
    int lane = threadIdx.x;
    RowP rp = row_params(p, b);
    float la = log2f(rp.aA), lr = log2f(rp.aR);
    float sig[4];
#pragma unroll
    for (int i = 0; i < 4; i++) {
        float j = (float)(4 * lane + 1 + i);
        sig[i] = exp2f(la * ((float)LSEG - j) + lr * j);
    }
    float sig0 = (lane == 0) ? exp2f(la * (float)LSEG) : 0.0f;
    const float NI = __int_as_float(0xff800000);

    float u = -g_v[(size_t)b * NP + 1];          // u_0 = -v[1]
    if (lane == 0) g_U[b * SSEG + 0] = u;

    const float* Tb = g_t + (size_t)b * SSEG * TSTR;
    float4 ta[PF];
    float t0a[PF];
#pragma unroll
    for (int k = 0; k < PF; k++) {
        const float* ts = Tb + (size_t)k * TSTR;
        ta[k]  = reinterpret_cast<const float4*>(ts + 32)[lane];
        t0a[k] = ts[0];
    }

    // SSEG iterations total; last one (s = NMAPS) computes a discarded value.
    for (int sb = 0; sb < SSEG; sb += PF) {
#pragma unroll
        for (int j = 0; j < PF; ++j) {           // compile-time slot -> regs
            int s = sb + j;
            float4 A = ta[j];
            float t0v = (lane == 0) ? t0a[j] : NI;
            int sp = s + PF;
            if (sp < SSEG) {
                const float* ts = Tb + (size_t)sp * TSTR;
                ta[j]  = reinterpret_cast<const float4*>(ts + 32)[lane];
                t0a[j] = ts[0];
            }
            float m0 = fmaf(sig[0], u, A.x);
            float m1 = fmaf(sig[1], u, A.y);
            float m2 = fmaf(sig[2], u, A.z);
            float m3 = fmaf(sig[3], u, A.w);
            float m4 = fmaf(sig0, u, t0v);       // lanes!=0: fma(0,u,-inf) = -inf
            float m = fmaxf(fmaxf(fmaxf(m0, m1), fmaxf(m2, m3)), m4);
            // monotone float->u32 map, warp allreduce max (REDUX.UMAX), map back
            unsigned bm = __float_as_uint(m);
            unsigned mm = bm ^ (((unsigned)((int)bm >> 31)) | 0x80000000u);
            unsigned rm = __reduce_max_sync(0xffffffffu, mm);
            u = __uint_as_float((rm & 0x80000000u) ? (rm ^ 0x80000000u) : ~rm);
            if (lane == 0 && (s + 1) < SSEG) g_U[b * SSEG + s + 1] = u;
        }
    }
}

// ---------------- Kernel 4: per-segment rerun + fused output ---------------
#define STEPF(C) do { float c_ = (C); u = fmaxf(fmaf(aA, u, c_), fmaf(aR, u, c_)); } while (0)

__device__ __forceinline__ float emitv(float xi, float w, float q, float gmk) {
    float y = fmaxf(q * w, -96.0f);
    float val = xi * exp10f(-y / 20.0f) * gmk;
    return isfinite(val) ? val : 0.0f;
}

__global__ void k_apply(const float* __restrict__ x, const float* __restrict__ p,
                        float* __restrict__ out) {
    int tid = blockIdx.x * blockDim.x + threadIdx.x;   // 65536 threads
    int b = tid >> 12;
    int s = tid & (SSEG - 1);
    RowP r = row_params(p, b);
    float aA = r.aA, aR = r.aR, q = r.q, gmk = r.gmk;
    float u = g_U[(b << 12) + s];

    const float4* V4 = reinterpret_cast<const float4*>(g_v) + (size_t)b * (NP / 4) + s * (LSEG / 4);
    const float4* X4 = reinterpret_cast<const float4*>(x) + (size_t)b * (NSAMP / 4) + s * (LSEG / 4);
    float4* O4 = reinterpret_cast<float4*>(out) + (size_t)b * (NSAMP / 4) + s * (LSEG / 4);

    float4 cur = V4[0];
#pragma unroll 4
    for (int g = 0; g < LSEG / 4; ++g) {
        float4 nxt = V4[g + 1];          // last read hits zero padding (v_N = 0)
        float4 xv = X4[g];
        float4 o;
        o.x = emitv(xv.x, u + cur.y, q, gmk); STEPF(cur.y - cur.z);
        o.y = emitv(xv.y, u + cur.z, q, gmk); STEPF(cur.z - cur.w);
        o.z = emitv(xv.z, u + cur.w, q, gmk); STEPF(cur.w - nxt.x);
        o.w = emitv(xv.w, u + nxt.x, q, gmk); STEPF(nxt.x - nxt.y);
        O4[g] = o;
        cur = nxt;
    }
}

extern "C" void kernel_launch(void* const* d_in, const int* in_sizes, int n_in,
                              void* d_out, int out_size) {
    const float* x = (const float*)d_in[0];      // [16, 524288] f32
    const float* p = (const float*)d_in[1];      // [16, 6] f32
    float* out = (float*)d_out;

    int total = BROWS * (NSAMP / 4);
    k_xl<<<(total + 255) / 256, 256>>>(x, p);
    k_map<<<4096, 256>>>(p);                     // 8 warps/block, 2 maps/warp
    k_bound<<<BROWS, 32>>>(p);
    k_apply<<<(BROWS * SSEG) / 256, 256>>>(x, p, out);
}